// round 6
// baseline (speedup 1.0000x reference)
#include <cuda_runtime.h>
#include <cuda_bf16.h>
#include <cstdint>

// ---------------------------------------------------------------------------
// SupGCL_GConv: 3x [GEMM(64x64)+bias+relu] interleaved with 2x high-pass
// graph filter:  out = z - (sum_{j->i} z[j] + z[i]) / (cnt[i]*deg[i])
//   deg[i] = outdeg(i)+1, cnt[i] = indeg(i)+1  (self loops)
// Algebra: with acc = edge-only sum, inv = 1/(deg*cnt):
//   out = z*(1-inv) - acc*inv     (self-loop folded; acc needs zeroing only)
// Filter finalize fused into the NEXT gemm's x-tile load.
// Edge dtype (int32 vs int64) is detected at runtime — JAX default config
// silently downgrades jnp.int64 to int32.
// ---------------------------------------------------------------------------

#define N_NODES 100000
#define D 64
#define N_EDGES 1200000

__device__ __align__(16) float g_zA[(size_t)N_NODES * D];
__device__ __align__(16) float g_zB[(size_t)N_NODES * D];
__device__ __align__(16) float g_acc[(size_t)N_NODES * D];
__device__ __align__(8)  int2  g_edge[N_EDGES];   // decoded (src, dst) int32
__device__ int g_deg[N_NODES];
__device__ int g_cnt[N_NODES];
__device__ int g_is64;

// ---------------------------------------------------------------------------
__global__ void detect_dtype_kernel(const long long* __restrict__ ei) {
    // If the buffer is really int64, the first 8 values are valid node ids.
    // If it is int32, an int64 view packs two ids -> values >= 2^32 (w.h.p.).
    if (blockIdx.x == 0 && threadIdx.x == 0) {
        bool ok = true;
        for (int i = 0; i < 8; i++) {
            long long v = ei[i];
            if (v < 0 || v >= N_NODES) ok = false;
        }
        g_is64 = ok ? 1 : 0;
    }
}

__global__ void init_counts_kernel(int n) {
    int i = blockIdx.x * blockDim.x + threadIdx.x;
    if (i < n) { g_deg[i] = 1; g_cnt[i] = 1; }   // self loops
}

// Decode edge indices (int32 or int64) to interleaved int2 AND count degrees.
__global__ void edge_prep_kernel(const void* __restrict__ ei, int E, int n) {
    int e = blockIdx.x * blockDim.x + threadIdx.x;
    if (e >= E) return;
    int s, t;
    if (g_is64) {
        s = (int)((const long long*)ei)[e];
        t = (int)((const long long*)ei)[E + e];
    } else {
        s = ((const int*)ei)[e];
        t = ((const int*)ei)[E + e];
    }
    // defensive clamp: wrong-answer beats illegal-access if parsing is off
    if ((unsigned)s >= (unsigned)n) s = 0;
    if ((unsigned)t >= (unsigned)n) t = 0;
    g_edge[e] = make_int2(s, t);
    atomicAdd(&g_deg[s], 1);
    atomicAdd(&g_cnt[t], 1);
}

__global__ void zero_acc_kernel(int n4) {
    int i = blockIdx.x * blockDim.x + threadIdx.x;
    if (i < n4) reinterpret_cast<float4*>(g_acc)[i] = make_float4(0.f, 0.f, 0.f, 0.f);
}

// 16 threads per edge (one 16B quad each): gather z[src] quad, vector-reduce
// (no return) into acc[dst]. Index load is one 8B broadcast per 16 lanes.
// sel: 0 -> read g_zA, 1 -> read g_zB
__global__ void scatter_kernel(int E, int sel) {
    int tid = blockIdx.x * blockDim.x + threadIdx.x;
    if (tid >= E * 16) return;
    int e = tid >> 4;
    int q = tid & 15;
    int2 sd = __ldg(&g_edge[e]);
    const float* z = sel ? g_zB : g_zA;
    float4 v = *reinterpret_cast<const float4*>(z + (size_t)sd.x * D + q * 4);
    float*  p = g_acc + (size_t)sd.y * D + q * 4;
    asm volatile("red.global.add.v4.f32 [%0], {%1, %2, %3, %4};"
                 :: "l"(p), "f"(v.x), "f"(v.y), "f"(v.z), "f"(v.w)
                 : "memory");
}

// ---------------------------------------------------------------------------
// Tiled GEMM: out = relu(XV @ W + b)
// stage 0: X = Xext,  out = g_zA, no filter
// stage 1: X = g_zA,  out = g_zB, filter (uses g_acc, g_deg, g_cnt)
// stage 2: X = g_zB,  out = Oext, filter
// Block: 256 threads, 64 rows/block; each thread computes 4 rows x 4 cols.
// ---------------------------------------------------------------------------
__global__ __launch_bounds__(256, 4)
void gemm_relu_kernel(const float* __restrict__ Xext,
                      float* __restrict__ Oext,
                      const float* __restrict__ W,
                      const float* __restrict__ B,
                      int n, int stage) {
    __shared__ float Ws[D * D];
    __shared__ float xs[64 * D];
    const int tid = threadIdx.x;
    const int r0  = blockIdx.x * 64;

    const float* X   = (stage == 0) ? Xext : (stage == 1 ? g_zA : g_zB);
    float*       out = (stage == 0) ? g_zA : (stage == 1 ? g_zB : Oext);
    const int use_filter = (stage != 0);

    // load W (4096 floats) via float4
    {
        const float4* Wv  = reinterpret_cast<const float4*>(W);
        float4*       Wsv = reinterpret_cast<float4*>(Ws);
#pragma unroll
        for (int i = 0; i < 4; i++) Wsv[tid + 256 * i] = Wv[tid + 256 * i];
    }

    // load + (optionally) filter-finalize the 64x64 x tile
#pragma unroll
    for (int i = 0; i < 4; i++) {
        int idx  = tid + 256 * i;          // 0..1023
        int row  = idx >> 4;               // 0..63
        int qc   = idx & 15;               // 16B quad
        int grow = r0 + row;
        float4 v = make_float4(0.f, 0.f, 0.f, 0.f);
        if (grow < n) {
            v = *reinterpret_cast<const float4*>(X + (size_t)grow * D + qc * 4);
            if (use_filter) {
                float inv = 1.0f / ((float)g_deg[grow] * (float)g_cnt[grow]);
                float om  = 1.0f - inv;
                float4 a  = *reinterpret_cast<const float4*>(g_acc + (size_t)grow * D + qc * 4);
                v.x = v.x * om - a.x * inv;
                v.y = v.y * om - a.y * inv;
                v.z = v.z * om - a.z * inv;
                v.w = v.w * om - a.w * inv;
            }
        }
        *reinterpret_cast<float4*>(xs + row * D + qc * 4) = v;
    }
    __syncthreads();

    const int jj = tid & 15;   // column quad: cols 4*jj..4*jj+3
    const int ty = tid >> 4;   // rows ty, ty+16, ty+32, ty+48
    float4 acc4[4];
#pragma unroll
    for (int r = 0; r < 4; r++) acc4[r] = make_float4(0.f, 0.f, 0.f, 0.f);

#pragma unroll 8
    for (int k = 0; k < D; k++) {
        float4 w = *reinterpret_cast<const float4*>(Ws + k * D + jj * 4);
#pragma unroll
        for (int r = 0; r < 4; r++) {
            float xv = xs[(ty + 16 * r) * D + k];
            acc4[r].x = fmaf(xv, w.x, acc4[r].x);
            acc4[r].y = fmaf(xv, w.y, acc4[r].y);
            acc4[r].z = fmaf(xv, w.z, acc4[r].z);
            acc4[r].w = fmaf(xv, w.w, acc4[r].w);
        }
    }

    float4 bj = *reinterpret_cast<const float4*>(B + jj * 4);
#pragma unroll
    for (int r = 0; r < 4; r++) {
        int grow = r0 + ty + 16 * r;
        if (grow < n) {
            float4 o;
            o.x = fmaxf(acc4[r].x + bj.x, 0.f);
            o.y = fmaxf(acc4[r].y + bj.y, 0.f);
            o.z = fmaxf(acc4[r].z + bj.z, 0.f);
            o.w = fmaxf(acc4[r].w + bj.w, 0.f);
            *reinterpret_cast<float4*>(out + (size_t)grow * D + jj * 4) = o;
        }
    }
}

// ---------------------------------------------------------------------------
extern "C" void kernel_launch(void* const* d_in, const int* in_sizes, int n_in,
                              void* d_out, int out_size) {
    // Bind inputs by element count (robust to metadata ordering):
    //   x: 6,400,000   edge_index: 2,400,000   W: 4096 (x3)   b: 64 (x3)
    int ix = -1, ie = -1, iW[3] = {-1, -1, -1}, ib[3] = {-1, -1, -1};
    int nW = 0, nb = 0;
    for (int i = 0; i < n_in; i++) {
        int s = in_sizes[i];
        if (s == N_NODES * D)       ix = i;
        else if (s == 2 * N_EDGES)  ie = i;
        else if (s == D * D && nW < 3) iW[nW++] = i;
        else if (s == D && nb < 3)     ib[nb++] = i;
    }
    if (ix < 0 || ie < 0 || nW < 3 || nb < 3) {   // positional fallback
        ix = 0; ie = 1;
        iW[0] = 2; ib[0] = 3; iW[1] = 4; ib[1] = 5; iW[2] = 6; ib[2] = 7;
    }

    const float* x  = (const float*)d_in[ix];
    const void*  ei = d_in[ie];
    const float* W1 = (const float*)d_in[iW[0]];
    const float* b1 = (const float*)d_in[ib[0]];
    const float* W2 = (const float*)d_in[iW[1]];
    const float* b2 = (const float*)d_in[ib[1]];
    const float* W3 = (const float*)d_in[iW[2]];
    const float* b3 = (const float*)d_in[ib[2]];
    float* out = (float*)d_out;

    const int n = in_sizes[ix] / D;      // 100000
    const int E = in_sizes[ie] / 2;      // 1200000 (element count, dtype-free)

    const int gemm_blocks = (n + 63) / 64;
    const int n4 = n * (D / 4);          // float4 count of acc

    // dtype probe + degrees + index decode (shared by both filters)
    detect_dtype_kernel<<<1, 32>>>((const long long*)ei);
    init_counts_kernel<<<(n + 255) / 256, 256>>>(n);
    edge_prep_kernel<<<(E + 255) / 256, 256>>>(ei, E, n);

    // layer 1: x -> g_zA
    gemm_relu_kernel<<<gemm_blocks, 256>>>(x, nullptr, W1, b1, n, 0);

    // filter 1: scatter g_zA -> g_acc
    zero_acc_kernel<<<(n4 + 255) / 256, 256>>>(n4);
    scatter_kernel<<<(E * 16 + 255) / 256, 256>>>(E, 0);

    // layer 2 (filter finalize fused into x-tile load): g_zA -> g_zB
    gemm_relu_kernel<<<gemm_blocks, 256>>>(nullptr, nullptr, W2, b2, n, 1);

    // filter 2: scatter g_zB -> g_acc
    zero_acc_kernel<<<(n4 + 255) / 256, 256>>>(n4);
    scatter_kernel<<<(E * 16 + 255) / 256, 256>>>(E, 1);

    // layer 3: g_zB -> d_out
    gemm_relu_kernel<<<gemm_blocks, 256>>>(nullptr, out, W3, b3, n, 2);
}